// round 7
// baseline (speedup 1.0000x reference)
#include <cuda_runtime.h>
#include <cstdint>
#include <math_constants.h>

#define D        64
#define KC       512
#define KHALF    256
#define CHUNKS   32          // 8-code chunks per phase-half (split 16/16 across warp pairs)
#define MT       128         // rows per tile
#define TILES    2048        // 262144 / 128
#define NROWS    262144
#define TPB      256
#define GRID     148
#define XSTRIDE  68          // padded row stride (floats) -> conflict-free frags

// ---- smem layout (float offsets) ----
#define OFF_XHI   0
#define OFF_XLO   (MT * XSTRIDE)                 // 8704
#define OFF_EHI   (OFF_XLO + MT * XSTRIDE)       // 17408 (Epack hi: 4096 float4)
#define OFF_ELO   (OFF_EHI + 16384)              // Epack lo
#define OFF_NRM   (OFF_ELO + 16384)
#define OFF_RSQ   (OFF_NRM + KHALF)
#define OFF_BEST  (OFF_RSQ + MT)
#define OFF_BK    (OFF_BEST + MT)
#define OFF_WSUM  (OFF_BK + MT)
#define SM_FLOATS (OFF_WSUM + 8)
#define SM_BYTES  (SM_FLOATS * 4)                // ~203 KB

__device__ float        g_best[NROWS];
__device__ int          g_bestk[NROWS];
__device__ float        g_cta[GRID];
__device__ unsigned int g_done = 0;

// tf32 cvt needs a .b32 destination register (NOT .f32).
__device__ __forceinline__ float to_tf32(float v) {
    uint32_t u;
    asm("cvt.rn.tf32.f32 %0, %1;" : "=r"(u) : "f"(v));
    return __uint_as_float(u);
}

// m16n8k8 tf32 mma: C(16x8,f32) += A(16x8) * B(8x8)
__device__ __forceinline__ void mma_tf32(float& c0, float& c1, float& c2, float& c3,
                                         float a0, float a1, float a2, float a3,
                                         float b0, float b1) {
    asm volatile(
        "mma.sync.aligned.m16n8k8.row.col.f32.tf32.tf32.f32 "
        "{%0,%1,%2,%3}, {%4,%5,%6,%7}, {%8,%9}, {%0,%1,%2,%3};"
        : "+f"(c0), "+f"(c1), "+f"(c2), "+f"(c3)
        : "r"(__float_as_uint(a0)), "r"(__float_as_uint(a1)),
          "r"(__float_as_uint(a2)), "r"(__float_as_uint(a3)),
          "r"(__float_as_uint(b0)), "r"(__float_as_uint(b1)));
}

__global__ void __launch_bounds__(TPB, 1)
vq_main(const float* __restrict__ x, const float* __restrict__ emb,
        float* __restrict__ out, int out_size) {
    extern __shared__ float sm[];
    const int tid  = threadIdx.x;
    const int wid  = tid >> 5;
    const int lane = tid & 31;
    const int g    = lane >> 2;   // groupID
    const int tig  = lane & 3;    // thread-in-group
    const int ch   = wid >> 2;    // code half: 0 -> chunks 0-15, 1 -> 16-31
    const int rg   = wid & 3;     // row group: 32 rows each

    float4* EH4 = (float4*)&sm[OFF_EHI];
    float4* EL4 = (float4*)&sm[OFF_ELO];
    int*    sBk = (int*)&sm[OFF_BK];

    float ctaAcc = 0.f;

    for (int phase = 0; phase < 2; phase++) {
        const int kb = phase * KHALF;

        // ---- build E fragment-pack (hi/lo tf32) for this half ----
        for (int slot = tid; slot < CHUNKS * 4 * 32; slot += TPB) {
            const int n  = slot >> 7;
            const int s2 = (slot >> 5) & 3;
            const int l  = slot & 31;
            const int lg = l >> 2, lt = l & 3;
            const float* er = emb + (size_t)(kb + n * 8 + lg) * D;
            const int c0 = 16 * s2 + lt;
            float v0 = er[c0], v1 = er[c0 + 4], v2 = er[c0 + 8], v3 = er[c0 + 12];
            float h0 = to_tf32(v0), h1 = to_tf32(v1), h2 = to_tf32(v2), h3 = to_tf32(v3);
            EH4[slot] = make_float4(h0, h1, h2, h3);
            EL4[slot] = make_float4(to_tf32(v0 - h0), to_tf32(v1 - h1),
                                    to_tf32(v2 - h2), to_tf32(v3 - h3));
        }
        // per-code norms, validated left-to-right scalar order
        {
            const float* er = emb + (size_t)(kb + tid) * D;
            float s = 0.f;
            #pragma unroll
            for (int d = 0; d < D; d++) s += er[d] * er[d];
            sm[OFF_NRM + tid] = s;
        }
        __syncthreads();

        for (int t = blockIdx.x; t < TILES; t += GRID) {
            const float4* xb = (const float4*)(x + (size_t)t * (MT * D));

            // ---- build X tile hi/lo (padded, stride 68) ----
            #pragma unroll
            for (int it = 0; it < 8; it++) {
                const int i = it * TPB + tid;
                float4 v = xb[i];
                const int r = i >> 4, c4 = i & 15;
                float4 h, l;
                h.x = to_tf32(v.x); h.y = to_tf32(v.y);
                h.z = to_tf32(v.z); h.w = to_tf32(v.w);
                l.x = to_tf32(v.x - h.x); l.y = to_tf32(v.y - h.y);
                l.z = to_tf32(v.z - h.z); l.w = to_tf32(v.w - h.w);
                *(float4*)&sm[OFF_XHI + r * XSTRIDE + c4 * 4] = h;
                *(float4*)&sm[OFF_XLO + r * XSTRIDE + c4 * 4] = l;
            }
            // rowsq: one thread per row, validated order
            if (tid < MT) {
                const float4* xr = xb + tid * 16;
                float rowsq = 0.f;
                #pragma unroll
                for (int i = 0; i < 16; i++) {
                    float4 v = xr[i];
                    rowsq += ((v.x * v.x + v.y * v.y) + v.z * v.z) + v.w * v.w;
                }
                sm[OFF_RSQ + tid] = rowsq;
            }
            __syncthreads();

            // ---- per-warp: 32 rows x 128 codes via mma ----
            const int rb = rg * 32;
            const int ra0 = rb + g,      ra1 = rb + 8 + g;    // A tile 0
            const int rb0 = rb + 16 + g, rb1 = rb + 24 + g;   // A tile 1

            float A0h[32], A0l[32], A1h[32], A1l[32];
            #pragma unroll
            for (int s = 0; s < 8; s++) {
                const int c = 8 * s + tig;
                A0h[4*s+0] = sm[OFF_XHI + ra0 * XSTRIDE + c];
                A0h[4*s+1] = sm[OFF_XHI + ra1 * XSTRIDE + c];
                A0h[4*s+2] = sm[OFF_XHI + ra0 * XSTRIDE + c + 4];
                A0h[4*s+3] = sm[OFF_XHI + ra1 * XSTRIDE + c + 4];
                A0l[4*s+0] = sm[OFF_XLO + ra0 * XSTRIDE + c];
                A0l[4*s+1] = sm[OFF_XLO + ra1 * XSTRIDE + c];
                A0l[4*s+2] = sm[OFF_XLO + ra0 * XSTRIDE + c + 4];
                A0l[4*s+3] = sm[OFF_XLO + ra1 * XSTRIDE + c + 4];
                A1h[4*s+0] = sm[OFF_XHI + rb0 * XSTRIDE + c];
                A1h[4*s+1] = sm[OFF_XHI + rb1 * XSTRIDE + c];
                A1h[4*s+2] = sm[OFF_XHI + rb0 * XSTRIDE + c + 4];
                A1h[4*s+3] = sm[OFF_XHI + rb1 * XSTRIDE + c + 4];
                A1l[4*s+0] = sm[OFF_XLO + rb0 * XSTRIDE + c];
                A1l[4*s+1] = sm[OFF_XLO + rb1 * XSTRIDE + c];
                A1l[4*s+2] = sm[OFF_XLO + rb0 * XSTRIDE + c + 4];
                A1l[4*s+3] = sm[OFF_XLO + rb1 * XSTRIDE + c + 4];
            }
            const float rs0 = sm[OFF_RSQ + ra0], rs1 = sm[OFF_RSQ + ra1];
            const float rs2 = sm[OFF_RSQ + rb0], rs3 = sm[OFF_RSQ + rb1];

            float best0 = CUDART_INF_F, best1 = CUDART_INF_F;
            float best2 = CUDART_INF_F, best3 = CUDART_INF_F;
            int bk0 = 0, bk1 = 0, bk2 = 0, bk3 = 0;

            #pragma unroll 2
            for (int np = 0; np < 16; np++) {
                const int n = ch * 16 + np;
                float4 BH[4], BL[4];
                #pragma unroll
                for (int s2 = 0; s2 < 4; s2++) {
                    BH[s2] = EH4[(n * 4 + s2) * 32 + lane];
                    BL[s2] = EL4[(n * 4 + s2) * 32 + lane];
                }
                // hh accumulators + fused cross (hl+lh) accumulators, per A tile
                float h00=0.f,h01=0.f,h02=0.f,h03=0.f, x00=0.f,x01=0.f,x02=0.f,x03=0.f;
                float h10=0.f,h11=0.f,h12=0.f,h13=0.f, x10=0.f,x11=0.f,x12=0.f,x13=0.f;
                #pragma unroll
                for (int s = 0; s < 8; s++) {
                    const float bh0 = (s & 1) ? BH[s>>1].z : BH[s>>1].x;
                    const float bh1 = (s & 1) ? BH[s>>1].w : BH[s>>1].y;
                    const float bl0 = (s & 1) ? BL[s>>1].z : BL[s>>1].x;
                    const float bl1 = (s & 1) ? BL[s>>1].w : BL[s>>1].y;
                    mma_tf32(h00,h01,h02,h03, A0h[4*s],A0h[4*s+1],A0h[4*s+2],A0h[4*s+3], bh0,bh1);
                    mma_tf32(x00,x01,x02,x03, A0h[4*s],A0h[4*s+1],A0h[4*s+2],A0h[4*s+3], bl0,bl1);
                    mma_tf32(x00,x01,x02,x03, A0l[4*s],A0l[4*s+1],A0l[4*s+2],A0l[4*s+3], bh0,bh1);
                    mma_tf32(h10,h11,h12,h13, A1h[4*s],A1h[4*s+1],A1h[4*s+2],A1h[4*s+3], bh0,bh1);
                    mma_tf32(x10,x11,x12,x13, A1h[4*s],A1h[4*s+1],A1h[4*s+2],A1h[4*s+3], bl0,bl1);
                    mma_tf32(x10,x11,x12,x13, A1l[4*s],A1l[4*s+1],A1l[4*s+2],A1l[4*s+3], bh0,bh1);
                }
                const float2 nv = *(const float2*)&sm[OFF_NRM + n * 8 + 2 * tig];
                const int k0 = kb + n * 8 + 2 * tig;

                float s00 = (rs0 + nv.x) - 2.0f * (h00 + x00);
                float s01 = (rs0 + nv.y) - 2.0f * (h01 + x01);
                float s10 = (rs1 + nv.x) - 2.0f * (h02 + x02);
                float s11 = (rs1 + nv.y) - 2.0f * (h03 + x03);
                float s20 = (rs2 + nv.x) - 2.0f * (h10 + x10);
                float s21 = (rs2 + nv.y) - 2.0f * (h11 + x11);
                float s30 = (rs3 + nv.x) - 2.0f * (h12 + x12);
                float s31 = (rs3 + nv.y) - 2.0f * (h13 + x13);
                if (s00 < best0) { best0 = s00; bk0 = k0; }
                if (s01 < best0) { best0 = s01; bk0 = k0 + 1; }
                if (s10 < best1) { best1 = s10; bk1 = k0; }
                if (s11 < best1) { best1 = s11; bk1 = k0 + 1; }
                if (s20 < best2) { best2 = s20; bk2 = k0; }
                if (s21 < best2) { best2 = s21; bk2 = k0 + 1; }
                if (s30 < best3) { best3 = s30; bk3 = k0; }
                if (s31 < best3) { best3 = s31; bk3 = k0 + 1; }
            }

            // merge across the 4 tig lanes (tie -> lowest k)
            #pragma unroll
            for (int off = 1; off <= 2; off <<= 1) {
                float o0 = __shfl_xor_sync(0xffffffffu, best0, off);
                int   k0s = __shfl_xor_sync(0xffffffffu, bk0,  off);
                float o1 = __shfl_xor_sync(0xffffffffu, best1, off);
                int   k1s = __shfl_xor_sync(0xffffffffu, bk1,  off);
                float o2 = __shfl_xor_sync(0xffffffffu, best2, off);
                int   k2s = __shfl_xor_sync(0xffffffffu, bk2,  off);
                float o3 = __shfl_xor_sync(0xffffffffu, best3, off);
                int   k3s = __shfl_xor_sync(0xffffffffu, bk3,  off);
                if (o0 < best0 || (o0 == best0 && k0s < bk0)) { best0 = o0; bk0 = k0s; }
                if (o1 < best1 || (o1 == best1 && k1s < bk1)) { best1 = o1; bk1 = k1s; }
                if (o2 < best2 || (o2 == best2 && k2s < bk2)) { best2 = o2; bk2 = k2s; }
                if (o3 < best3 || (o3 == best3 && k3s < bk3)) { best3 = o3; bk3 = k3s; }
            }

            // pair merge: code-half 0 writes, code-half 1 merges (its ks are larger,
            // so strict < preserves lowest-k tie semantics)
            if (ch == 0 && tig == 0) {
                sm[OFF_BEST + ra0] = best0; sBk[ra0] = bk0;
                sm[OFF_BEST + ra1] = best1; sBk[ra1] = bk1;
                sm[OFF_BEST + rb0] = best2; sBk[rb0] = bk2;
                sm[OFF_BEST + rb1] = best3; sBk[rb1] = bk3;
            }
            __syncthreads();
            if (ch == 1 && tig == 0) {
                float p0 = sm[OFF_BEST + ra0]; int q0 = sBk[ra0];
                float p1 = sm[OFF_BEST + ra1]; int q1 = sBk[ra1];
                float p2 = sm[OFF_BEST + rb0]; int q2 = sBk[rb0];
                float p3 = sm[OFF_BEST + rb1]; int q3 = sBk[rb1];
                if (best0 < p0) { p0 = best0; q0 = bk0; }
                if (best1 < p1) { p1 = best1; q1 = bk1; }
                if (best2 < p2) { p2 = best2; q2 = bk2; }
                if (best3 < p3) { p3 = best3; q3 = bk3; }
                if (phase == 0) {
                    const int gb = t * MT;
                    g_best[gb + ra0] = p0; g_bestk[gb + ra0] = q0;
                    g_best[gb + ra1] = p1; g_bestk[gb + ra1] = q1;
                    g_best[gb + rb0] = p2; g_bestk[gb + rb0] = q2;
                    g_best[gb + rb1] = p3; g_bestk[gb + rb1] = q3;
                } else {
                    // merge with phase-0 global results, then publish final
                    const int gb = t * MT;
                    float f0 = g_best[gb + ra0]; int e0 = g_bestk[gb + ra0];
                    float f1 = g_best[gb + ra1]; int e1 = g_bestk[gb + ra1];
                    float f2 = g_best[gb + rb0]; int e2 = g_bestk[gb + rb0];
                    float f3 = g_best[gb + rb1]; int e3 = g_bestk[gb + rb1];
                    if (p0 < f0) { f0 = p0; e0 = q0; }
                    if (p1 < f1) { f1 = p1; e1 = q1; }
                    if (p2 < f2) { f2 = p2; e2 = q2; }
                    if (p3 < f3) { f3 = p3; e3 = q3; }
                    sm[OFF_BEST + ra0] = f0; sBk[ra0] = e0;
                    sm[OFF_BEST + ra1] = f1; sBk[ra1] = e1;
                    sm[OFF_BEST + rb0] = f2; sBk[rb0] = e2;
                    sm[OFF_BEST + rb1] = f3; sBk[rb1] = e3;
                }
            }
            __syncthreads();

            if (phase == 1) {
                // gather + coalesced write of quantized rows
                float4* o4 = (float4*)(out + (size_t)t * (MT * D));
                const float4* e4 = (const float4*)emb;
                #pragma unroll
                for (int i4 = tid; i4 < MT * D / 4; i4 += TPB) {
                    const int r = i4 >> 4, dd = i4 & 15;
                    o4[i4] = e4[(size_t)sBk[r] * 16 + dd];
                }
                if (tid < MT) {
                    float v = sm[OFF_BEST + tid];
                    #pragma unroll
                    for (int off = 16; off > 0; off >>= 1)
                        v += __shfl_down_sync(0xffffffffu, v, off);
                    if ((tid & 31) == 0) sm[OFF_WSUM + (tid >> 5)] = v;
                }
                __syncthreads();
                if (tid == 0)
                    ctaAcc += ((sm[OFF_WSUM] + sm[OFF_WSUM+1]) + sm[OFF_WSUM+2]) + sm[OFF_WSUM+3];
            }
            __syncthreads();
        }
        __syncthreads();   // before Epack is rebuilt for next phase
    }

    // ---- fused finalize: last CTA computes the two loss scalars ----
    if (tid == 0) {
        g_cta[blockIdx.x] = ctaAcc;
        __threadfence();
        unsigned int prev = atomicAdd(&g_done, 1);
        if (prev == GRID - 1) {
            float s = 0.f;
            for (int i = 0; i < GRID; i++) s += g_cta[i];
            float mean = s / (float)((long long)NROWS * D);
            out[out_size - 2] = mean;          // codebook_loss
            out[out_size - 1] = 0.25f * mean;  // commitment_loss (BETA)
            g_done = 0;                        // reset for next graph replay
        }
    }
}

extern "C" void kernel_launch(void* const* d_in, const int* in_sizes, int n_in,
                              void* d_out, int out_size) {
    const float* x   = (const float*)d_in[0];   // inputs (B,H,W,D) f32
    const float* emb = (const float*)d_in[1];   // embeddings (K,D) f32
    float* out = (float*)d_out;

    cudaFuncSetAttribute(vq_main, cudaFuncAttributeMaxDynamicSharedMemorySize,
                         SM_BYTES);
    vq_main<<<GRID, TPB, SM_BYTES>>>(x, emb, out, out_size);
}

// round 9
// speedup vs baseline: 1.0218x; 1.0218x over previous
#include <cuda_runtime.h>
#include <cstdint>
#include <math_constants.h>

#define D        64
#define KC       512
#define KHALF    256
#define CHUNKS   32          // 8-code chunks per phase-half (split 16/16 across warp pairs)
#define MT       128         // rows per tile
#define TILES    2048        // 262144 / 128
#define NROWS    262144
#define TPB      256
#define GRID     148
#define XSTRIDE  68          // padded row stride (floats) -> conflict-free frags

// ---- smem layout (float offsets) ----
#define OFF_XHI   0
#define OFF_XLO   (MT * XSTRIDE)                 // 8704
#define OFF_EHI   (OFF_XLO + MT * XSTRIDE)       // 17408 (Epack hi: 4096 float4)
#define OFF_ELO   (OFF_EHI + 16384)              // Epack lo
#define OFF_NRM   (OFF_ELO + 16384)
#define OFF_RSQ   (OFF_NRM + KHALF)
#define OFF_BEST  (OFF_RSQ + MT)
#define OFF_BK    (OFF_BEST + MT)
#define OFF_WSUM  (OFF_BK + MT)
#define SM_FLOATS (OFF_WSUM + 8)
#define SM_BYTES  (SM_FLOATS * 4)                // ~203 KB

__device__ float        g_best[NROWS];
__device__ int          g_bestk[NROWS];
__device__ float        g_cta[GRID];
__device__ unsigned int g_done = 0;

// tf32 cvt needs a .b32 destination register (NOT .f32).
__device__ __forceinline__ float to_tf32(float v) {
    uint32_t u;
    asm("cvt.rn.tf32.f32 %0, %1;" : "=r"(u) : "f"(v));
    return __uint_as_float(u);
}

// m16n8k8 tf32 mma: C(16x8,f32) += A(16x8) * B(8x8)
__device__ __forceinline__ void mma_tf32(float& c0, float& c1, float& c2, float& c3,
                                         float a0, float a1, float a2, float a3,
                                         float b0, float b1) {
    asm volatile(
        "mma.sync.aligned.m16n8k8.row.col.f32.tf32.tf32.f32 "
        "{%0,%1,%2,%3}, {%4,%5,%6,%7}, {%8,%9}, {%0,%1,%2,%3};"
        : "+f"(c0), "+f"(c1), "+f"(c2), "+f"(c3)
        : "r"(__float_as_uint(a0)), "r"(__float_as_uint(a1)),
          "r"(__float_as_uint(a2)), "r"(__float_as_uint(a3)),
          "r"(__float_as_uint(b0)), "r"(__float_as_uint(b1)));
}

__global__ void __launch_bounds__(TPB, 1)
vq_main(const float* __restrict__ x, const float* __restrict__ emb,
        float* __restrict__ out, int out_size) {
    extern __shared__ float sm[];
    const int tid  = threadIdx.x;
    const int wid  = tid >> 5;
    const int lane = tid & 31;
    const int g    = lane >> 2;   // groupID
    const int tig  = lane & 3;    // thread-in-group
    const int ch   = wid >> 2;    // code half: 0 -> chunks 0-15, 1 -> 16-31
    const int rg   = wid & 3;     // row group: 32 rows each

    float4* EH4 = (float4*)&sm[OFF_EHI];
    float4* EL4 = (float4*)&sm[OFF_ELO];
    int*    sBk = (int*)&sm[OFF_BK];

    float ctaAcc = 0.f;

    for (int phase = 0; phase < 2; phase++) {
        const int kb = phase * KHALF;

        // ---- build E fragment-pack (hi/lo tf32) for this half ----
        for (int slot = tid; slot < CHUNKS * 4 * 32; slot += TPB) {
            const int n  = slot >> 7;
            const int s2 = (slot >> 5) & 3;
            const int l  = slot & 31;
            const int lg = l >> 2, lt = l & 3;
            const float* er = emb + (size_t)(kb + n * 8 + lg) * D;
            const int c0 = 16 * s2 + lt;
            float v0 = er[c0], v1 = er[c0 + 4], v2 = er[c0 + 8], v3 = er[c0 + 12];
            float h0 = to_tf32(v0), h1 = to_tf32(v1), h2 = to_tf32(v2), h3 = to_tf32(v3);
            EH4[slot] = make_float4(h0, h1, h2, h3);
            EL4[slot] = make_float4(to_tf32(v0 - h0), to_tf32(v1 - h1),
                                    to_tf32(v2 - h2), to_tf32(v3 - h3));
        }
        // per-code norms, validated left-to-right scalar order
        {
            const float* er = emb + (size_t)(kb + tid) * D;
            float s = 0.f;
            #pragma unroll
            for (int d = 0; d < D; d++) s += er[d] * er[d];
            sm[OFF_NRM + tid] = s;
        }
        __syncthreads();

        for (int t = blockIdx.x; t < TILES; t += GRID) {
            const float4* xb = (const float4*)(x + (size_t)t * (MT * D));

            // ---- build X tile hi/lo (padded, stride 68) ----
            #pragma unroll
            for (int it = 0; it < 8; it++) {
                const int i = it * TPB + tid;
                float4 v = xb[i];
                const int r = i >> 4, c4 = i & 15;
                float4 h, l;
                h.x = to_tf32(v.x); h.y = to_tf32(v.y);
                h.z = to_tf32(v.z); h.w = to_tf32(v.w);
                l.x = to_tf32(v.x - h.x); l.y = to_tf32(v.y - h.y);
                l.z = to_tf32(v.z - h.z); l.w = to_tf32(v.w - h.w);
                *(float4*)&sm[OFF_XHI + r * XSTRIDE + c4 * 4] = h;
                *(float4*)&sm[OFF_XLO + r * XSTRIDE + c4 * 4] = l;
            }
            // rowsq: one thread per row, validated order
            if (tid < MT) {
                const float4* xr = xb + tid * 16;
                float rowsq = 0.f;
                #pragma unroll
                for (int i = 0; i < 16; i++) {
                    float4 v = xr[i];
                    rowsq += ((v.x * v.x + v.y * v.y) + v.z * v.z) + v.w * v.w;
                }
                sm[OFF_RSQ + tid] = rowsq;
            }
            __syncthreads();

            // ---- per-warp: 32 rows x 128 codes via mma ----
            const int rb = rg * 32;
            const int ra0 = rb + g,      ra1 = rb + 8 + g;    // A tile 0
            const int rb0 = rb + 16 + g, rb1 = rb + 24 + g;   // A tile 1

            float A0h[32], A0l[32], A1h[32], A1l[32];
            #pragma unroll
            for (int s = 0; s < 8; s++) {
                const int c = 8 * s + tig;
                A0h[4*s+0] = sm[OFF_XHI + ra0 * XSTRIDE + c];
                A0h[4*s+1] = sm[OFF_XHI + ra1 * XSTRIDE + c];
                A0h[4*s+2] = sm[OFF_XHI + ra0 * XSTRIDE + c + 4];
                A0h[4*s+3] = sm[OFF_XHI + ra1 * XSTRIDE + c + 4];
                A0l[4*s+0] = sm[OFF_XLO + ra0 * XSTRIDE + c];
                A0l[4*s+1] = sm[OFF_XLO + ra1 * XSTRIDE + c];
                A0l[4*s+2] = sm[OFF_XLO + ra0 * XSTRIDE + c + 4];
                A0l[4*s+3] = sm[OFF_XLO + ra1 * XSTRIDE + c + 4];
                A1h[4*s+0] = sm[OFF_XHI + rb0 * XSTRIDE + c];
                A1h[4*s+1] = sm[OFF_XHI + rb1 * XSTRIDE + c];
                A1h[4*s+2] = sm[OFF_XHI + rb0 * XSTRIDE + c + 4];
                A1h[4*s+3] = sm[OFF_XHI + rb1 * XSTRIDE + c + 4];
                A1l[4*s+0] = sm[OFF_XLO + rb0 * XSTRIDE + c];
                A1l[4*s+1] = sm[OFF_XLO + rb1 * XSTRIDE + c];
                A1l[4*s+2] = sm[OFF_XLO + rb0 * XSTRIDE + c + 4];
                A1l[4*s+3] = sm[OFF_XLO + rb1 * XSTRIDE + c + 4];
            }
            const float rs0 = sm[OFF_RSQ + ra0], rs1 = sm[OFF_RSQ + ra1];
            const float rs2 = sm[OFF_RSQ + rb0], rs3 = sm[OFF_RSQ + rb1];

            float best0 = CUDART_INF_F, best1 = CUDART_INF_F;
            float best2 = CUDART_INF_F, best3 = CUDART_INF_F;
            int bk0 = 0, bk1 = 0, bk2 = 0, bk3 = 0;

            #pragma unroll 1
            for (int np = 0; np < 16; np++) {
                const int n = ch * 16 + np;
                float4 BH[4], BL[4];
                #pragma unroll
                for (int s2 = 0; s2 < 4; s2++) {
                    BH[s2] = EH4[(n * 4 + s2) * 32 + lane];
                    BL[s2] = EL4[(n * 4 + s2) * 32 + lane];
                }
                // SIX independent accumulator chains per np (one touch per k-step
                // each): hh tile0/1, hi*lo tile0/1, lo*hi tile0/1. Same-chain
                // reissue gap = 6 MMA issues (~48 cyc) > HMMA latency -> no stalls.
                float h00=0.f,h01=0.f,h02=0.f,h03=0.f;
                float h10=0.f,h11=0.f,h12=0.f,h13=0.f;
                float p00=0.f,p01=0.f,p02=0.f,p03=0.f;
                float p10=0.f,p11=0.f,p12=0.f,p13=0.f;
                float q00=0.f,q01=0.f,q02=0.f,q03=0.f;
                float q10=0.f,q11=0.f,q12=0.f,q13=0.f;
                #pragma unroll
                for (int s = 0; s < 8; s++) {
                    const float bh0 = (s & 1) ? BH[s>>1].z : BH[s>>1].x;
                    const float bh1 = (s & 1) ? BH[s>>1].w : BH[s>>1].y;
                    const float bl0 = (s & 1) ? BL[s>>1].z : BL[s>>1].x;
                    const float bl1 = (s & 1) ? BL[s>>1].w : BL[s>>1].y;
                    mma_tf32(h00,h01,h02,h03, A0h[4*s],A0h[4*s+1],A0h[4*s+2],A0h[4*s+3], bh0,bh1);
                    mma_tf32(h10,h11,h12,h13, A1h[4*s],A1h[4*s+1],A1h[4*s+2],A1h[4*s+3], bh0,bh1);
                    mma_tf32(p00,p01,p02,p03, A0h[4*s],A0h[4*s+1],A0h[4*s+2],A0h[4*s+3], bl0,bl1);
                    mma_tf32(p10,p11,p12,p13, A1h[4*s],A1h[4*s+1],A1h[4*s+2],A1h[4*s+3], bl0,bl1);
                    mma_tf32(q00,q01,q02,q03, A0l[4*s],A0l[4*s+1],A0l[4*s+2],A0l[4*s+3], bh0,bh1);
                    mma_tf32(q10,q11,q12,q13, A1l[4*s],A1l[4*s+1],A1l[4*s+2],A1l[4*s+3], bh0,bh1);
                }
                const float2 nv = *(const float2*)&sm[OFF_NRM + n * 8 + 2 * tig];
                const int k0 = kb + n * 8 + 2 * tig;

                float s00 = (rs0 + nv.x) - 2.0f * ((h00 + p00) + q00);
                float s01 = (rs0 + nv.y) - 2.0f * ((h01 + p01) + q01);
                float s10 = (rs1 + nv.x) - 2.0f * ((h02 + p02) + q02);
                float s11 = (rs1 + nv.y) - 2.0f * ((h03 + p03) + q03);
                float s20 = (rs2 + nv.x) - 2.0f * ((h10 + p10) + q10);
                float s21 = (rs2 + nv.y) - 2.0f * ((h11 + p11) + q11);
                float s30 = (rs3 + nv.x) - 2.0f * ((h12 + p12) + q12);
                float s31 = (rs3 + nv.y) - 2.0f * ((h13 + p13) + q13);
                if (s00 < best0) { best0 = s00; bk0 = k0; }
                if (s01 < best0) { best0 = s01; bk0 = k0 + 1; }
                if (s10 < best1) { best1 = s10; bk1 = k0; }
                if (s11 < best1) { best1 = s11; bk1 = k0 + 1; }
                if (s20 < best2) { best2 = s20; bk2 = k0; }
                if (s21 < best2) { best2 = s21; bk2 = k0 + 1; }
                if (s30 < best3) { best3 = s30; bk3 = k0; }
                if (s31 < best3) { best3 = s31; bk3 = k0 + 1; }
            }

            // merge across the 4 tig lanes (tie -> lowest k)
            #pragma unroll
            for (int off = 1; off <= 2; off <<= 1) {
                float o0 = __shfl_xor_sync(0xffffffffu, best0, off);
                int   k0s = __shfl_xor_sync(0xffffffffu, bk0,  off);
                float o1 = __shfl_xor_sync(0xffffffffu, best1, off);
                int   k1s = __shfl_xor_sync(0xffffffffu, bk1,  off);
                float o2 = __shfl_xor_sync(0xffffffffu, best2, off);
                int   k2s = __shfl_xor_sync(0xffffffffu, bk2,  off);
                float o3 = __shfl_xor_sync(0xffffffffu, best3, off);
                int   k3s = __shfl_xor_sync(0xffffffffu, bk3,  off);
                if (o0 < best0 || (o0 == best0 && k0s < bk0)) { best0 = o0; bk0 = k0s; }
                if (o1 < best1 || (o1 == best1 && k1s < bk1)) { best1 = o1; bk1 = k1s; }
                if (o2 < best2 || (o2 == best2 && k2s < bk2)) { best2 = o2; bk2 = k2s; }
                if (o3 < best3 || (o3 == best3 && k3s < bk3)) { best3 = o3; bk3 = k3s; }
            }

            // pair merge: code-half 0 writes, code-half 1 merges (its ks are larger,
            // so strict < preserves lowest-k tie semantics)
            if (ch == 0 && tig == 0) {
                sm[OFF_BEST + ra0] = best0; sBk[ra0] = bk0;
                sm[OFF_BEST + ra1] = best1; sBk[ra1] = bk1;
                sm[OFF_BEST + rb0] = best2; sBk[rb0] = bk2;
                sm[OFF_BEST + rb1] = best3; sBk[rb1] = bk3;
            }
            __syncthreads();
            if (ch == 1 && tig == 0) {
                float p0 = sm[OFF_BEST + ra0]; int q0 = sBk[ra0];
                float p1 = sm[OFF_BEST + ra1]; int q1 = sBk[ra1];
                float p2 = sm[OFF_BEST + rb0]; int q2 = sBk[rb0];
                float p3 = sm[OFF_BEST + rb1]; int q3 = sBk[rb1];
                if (best0 < p0) { p0 = best0; q0 = bk0; }
                if (best1 < p1) { p1 = best1; q1 = bk1; }
                if (best2 < p2) { p2 = best2; q2 = bk2; }
                if (best3 < p3) { p3 = best3; q3 = bk3; }
                if (phase == 0) {
                    const int gb = t * MT;
                    g_best[gb + ra0] = p0; g_bestk[gb + ra0] = q0;
                    g_best[gb + ra1] = p1; g_bestk[gb + ra1] = q1;
                    g_best[gb + rb0] = p2; g_bestk[gb + rb0] = q2;
                    g_best[gb + rb1] = p3; g_bestk[gb + rb1] = q3;
                } else {
                    const int gb = t * MT;
                    float f0 = g_best[gb + ra0]; int e0 = g_bestk[gb + ra0];
                    float f1 = g_best[gb + ra1]; int e1 = g_bestk[gb + ra1];
                    float f2 = g_best[gb + rb0]; int e2 = g_bestk[gb + rb0];
                    float f3 = g_best[gb + rb1]; int e3 = g_bestk[gb + rb1];
                    if (p0 < f0) { f0 = p0; e0 = q0; }
                    if (p1 < f1) { f1 = p1; e1 = q1; }
                    if (p2 < f2) { f2 = p2; e2 = q2; }
                    if (p3 < f3) { f3 = p3; e3 = q3; }
                    sm[OFF_BEST + ra0] = f0; sBk[ra0] = e0;
                    sm[OFF_BEST + ra1] = f1; sBk[ra1] = e1;
                    sm[OFF_BEST + rb0] = f2; sBk[rb0] = e2;
                    sm[OFF_BEST + rb1] = f3; sBk[rb1] = e3;
                }
            }
            __syncthreads();

            if (phase == 1) {
                // gather + coalesced write of quantized rows
                float4* o4 = (float4*)(out + (size_t)t * (MT * D));
                const float4* e4 = (const float4*)emb;
                #pragma unroll
                for (int i4 = tid; i4 < MT * D / 4; i4 += TPB) {
                    const int r = i4 >> 4, dd = i4 & 15;
                    o4[i4] = e4[(size_t)sBk[r] * 16 + dd];
                }
                if (tid < MT) {
                    float v = sm[OFF_BEST + tid];
                    #pragma unroll
                    for (int off = 16; off > 0; off >>= 1)
                        v += __shfl_down_sync(0xffffffffu, v, off);
                    if ((tid & 31) == 0) sm[OFF_WSUM + (tid >> 5)] = v;
                }
                __syncthreads();
                if (tid == 0)
                    ctaAcc += ((sm[OFF_WSUM] + sm[OFF_WSUM+1]) + sm[OFF_WSUM+2]) + sm[OFF_WSUM+3];
            }
            __syncthreads();
        }
        __syncthreads();   // before Epack is rebuilt for next phase
    }

    // ---- fused finalize: last CTA computes the two loss scalars ----
    if (tid == 0) {
        g_cta[blockIdx.x] = ctaAcc;
        __threadfence();
        unsigned int prev = atomicAdd(&g_done, 1);
        if (prev == GRID - 1) {
            float s = 0.f;
            for (int i = 0; i < GRID; i++) s += g_cta[i];
            float mean = s / (float)((long long)NROWS * D);
            out[out_size - 2] = mean;          // codebook_loss
            out[out_size - 1] = 0.25f * mean;  // commitment_loss (BETA)
            g_done = 0;                        // reset for next graph replay
        }
    }
}

extern "C" void kernel_launch(void* const* d_in, const int* in_sizes, int n_in,
                              void* d_out, int out_size) {
    const float* x   = (const float*)d_in[0];   // inputs (B,H,W,D) f32
    const float* emb = (const float*)d_in[1];   // embeddings (K,D) f32
    float* out = (float*)d_out;

    cudaFuncSetAttribute(vq_main, cudaFuncAttributeMaxDynamicSharedMemorySize,
                         SM_BYTES);
    vq_main<<<GRID, TPB, SM_BYTES>>>(x, emb, out, out_size);
}